// round 7
// baseline (speedup 1.0000x reference)
#include <cuda_runtime.h>
#include <cstdint>
#include <cstddef>

// ---------------------------------------------------------------------------
// SparseDecoder: 4-layer masked MLP, B=64, widths 512->2048->4096->8192->16384
//
// v5: - split-K partial sums: every layer runs 512 CTAs (fixes grid-limited
//       occ=41% of v4) at unchanged x-staging traffic
//     - per-chunk software pipeline: x(c+1)->regs, mask(c+1), W(c+1, RPW<=2)
//       prefetched during extraction of chunk c
//     - epilogue kernel: sum SK partials + bias + ReLU (no atomics)
// ---------------------------------------------------------------------------

#define MAXN 16384
#define BATCH 64

__device__ float g_bufA[MAXN * BATCH];        // activations, [N][64]
__device__ float g_bufB[MAXN * BATCH];
__device__ float g_part[2 * MAXN * BATCH];    // split-K partial sums (8.4 MB)
__device__ int   g_dtype[4];                  // 0=u8, 1=i32, 2=f32, 3=bf16

// ---------------------------------------------------------------------------
// Mask dtype detection (proven in v3/v4).
// ---------------------------------------------------------------------------
__global__ void detect_dtype_kernel(const void* m0, long n0, const void* m1, long n1,
                                    const void* m2, long n2, const void* m3, long n3) {
    const void* ms[4] = {m0, m1, m2, m3};
    long        ns[4] = {n0, n1, n2, n3};
    int L = blockIdx.x;
    const unsigned int* p = (const unsigned int*)ms[L];
    long nw = ns[L] >> 2;
    if (nw > 65536) nw = 65536;

    unsigned int f = 0;
    for (long i = threadIdx.x; i < nw; i += blockDim.x) {
        unsigned int w = __ldg(p + i);
        if (w == 0u) continue;
        if ((w & 0xFFFFu) == 0x3F80u) f |= 1u;                // bf16
        if (w == 0x3F800000u)         f |= 2u;                // f32
        if ((w & 0xFEFEFEFEu) == 0u && w > 1u) f |= 4u;       // u8
        if (w == 1u)                  f |= 8u;                // i32 (or u8 byte0)
    }
    __shared__ unsigned int sf;
    if (threadIdx.x == 0) sf = 0;
    __syncthreads();
    atomicOr(&sf, f);
    __syncthreads();
    if (threadIdx.x == 0) {
        unsigned int ff = sf;
        int dt;
        if      (ff & 1u) dt = 3;
        else if (ff & 2u) dt = 2;
        else if (ff & 4u) dt = 0;
        else if (ff & 8u) dt = 1;
        else              dt = 0;
        g_dtype[L] = dt;
    }
}

// ---------------------------------------------------------------------------
// Tiled transpose: dst[C][R] = src[R][C]
// ---------------------------------------------------------------------------
__global__ void transpose_kernel(const float* __restrict__ src,
                                 float* __restrict__ dst, int R, int C) {
    __shared__ float tile[32][33];
    int c0 = blockIdx.x * 32;
    int r0 = blockIdx.y * 32;
    int tx = threadIdx.x, ty = threadIdx.y;
    #pragma unroll
    for (int i = ty; i < 32; i += 8) {
        int r = r0 + i, c = c0 + tx;
        if (r < R && c < C) tile[i][tx] = src[(size_t)r * C + c];
    }
    __syncthreads();
    #pragma unroll
    for (int i = ty; i < 32; i += 8) {
        int c = c0 + i, r = r0 + tx;
        if (c < C && r < R) dst[(size_t)c * R + r] = tile[tx][i];
    }
}

// ---------------------------------------------------------------------------
// mask element index -> 4-bit nonzero nibble for lane's 4 columns
// ---------------------------------------------------------------------------
__device__ __forceinline__ unsigned int load_nib(const void* mask, size_t eidx, int dt) {
    if (dt == 0) {               // u8
        unsigned int v = __ldg((const unsigned int*)((const unsigned char*)mask + eidx));
        unsigned int c = __vcmpne4(v, 0u);
        return (c & 1u) | ((c >> 7) & 2u) | ((c >> 14) & 4u) | ((c >> 21) & 8u);
    } else if (dt == 3) {        // bf16
        uint2 v = __ldg((const uint2*)((const unsigned short*)mask + eidx));
        return (unsigned)((v.x & 0xFFFFu) != 0u)
             | ((unsigned)((v.x >> 16)     != 0u) << 1)
             | ((unsigned)((v.y & 0xFFFFu) != 0u) << 2)
             | ((unsigned)((v.y >> 16)     != 0u) << 3);
    } else {                     // i32 / f32
        uint4 v = __ldg((const uint4*)((const unsigned int*)mask + eidx));
        return (unsigned)(v.x != 0u)
             | ((unsigned)(v.y != 0u) << 1)
             | ((unsigned)(v.z != 0u) << 2)
             | ((unsigned)(v.w != 0u) << 3);
    }
}

// ---------------------------------------------------------------------------
// Split-K sparse partial: part[s] += (W*mask)[rows, koff:koff+kcols] @ x[koff:...]
// grid = (rowGroups, SK). 512 threads = 16 warps; warp owns RPW rows;
// lane owns batch elements 2l, 2l+1.
// ---------------------------------------------------------------------------
template <int RPW, int MINB>
__global__ __launch_bounds__(512, MINB)
void sparse_partial_kernel(const float* __restrict__ W,
                           const void*  __restrict__ mask,
                           const float* __restrict__ xin,   // [N_in][64]
                           float*       __restrict__ part,  // [SK][N_out][64]
                           int N_in, int kcols, int partElems, int layer) {
    __shared__ float sx[128 * 64];   // 32 KB x chunk

    const int tid  = threadIdx.x;
    const int lane = tid & 31;
    const int wid  = tid >> 5;
    const int row0 = blockIdx.x * (RPW * 16) + wid * RPW;
    const int koff = blockIdx.y * kcols;
    const int dt   = g_dtype[layer];
    const int nchunk = kcols >> 7;

    float accx[RPW], accy[RPW];
    #pragma unroll
    for (int r = 0; r < RPW; r++) { accx[r] = 0.f; accy[r] = 0.f; }

    // ---- preload chunk 0: x -> regs, mask -> nib, W (predicated) -> wv
    float4 xr[4];
    {
        const float4* src = (const float4*)(xin + (size_t)koff * BATCH);
        #pragma unroll
        for (int i = 0; i < 4; i++) xr[i] = __ldg(src + tid + i * 512);
    }
    unsigned int nib[RPW];
    float4       wv[RPW];
    #pragma unroll
    for (int r = 0; r < RPW; r++) {
        const size_t be = (size_t)(row0 + r) * N_in + koff + (lane << 2);
        nib[r] = load_nib(mask, be, dt);
        if (nib[r]) wv[r] = __ldg((const float4*)(W + be));
    }

    for (int c = 0; c < nchunk; ++c) {
        __syncthreads();                      // previous chunk consumed
        {
            float4* dst4 = (float4*)sx;
            #pragma unroll
            for (int i = 0; i < 4; i++) dst4[tid + i * 512] = xr[i];
        }
        __syncthreads();                      // chunk c staged

        const bool hasNext = (c + 1 < nchunk);
        unsigned int nibN[RPW];

        // prefetch x(c+1) and mask(c+1): latency covered by extraction below
        if (hasNext) {
            const float4* src = (const float4*)(xin + (size_t)(koff + (c + 1) * 128) * BATCH);
            #pragma unroll
            for (int i = 0; i < 4; i++) xr[i] = __ldg(src + tid + i * 512);
            #pragma unroll
            for (int r = 0; r < RPW; r++) {
                const size_t be = (size_t)(row0 + r) * N_in + koff + ((c + 1) << 7) + (lane << 2);
                nibN[r] = load_nib(mask, be, dt);
            }
        }

        // for RPW==4 (reg pressure) W is loaded in-iteration instead of prefetched
        if (RPW > 2) {
            #pragma unroll
            for (int r = 0; r < RPW; r++) {
                const size_t be = (size_t)(row0 + r) * N_in + koff + (c << 7) + (lane << 2);
                if (nib[r]) wv[r] = __ldg((const float4*)(W + be));
            }
        }

        // ---- extraction: per nz -> shfl W from owning lane + LDS.64 x + 2 FMA
        #pragma unroll
        for (int r = 0; r < RPW; r++) {
            #pragma unroll
            for (int sub = 0; sub < 4; ++sub) {
                unsigned int bm = __ballot_sync(0xffffffffu, (nib[r] >> sub) & 1u);
                const float wsub = (sub == 0) ? wv[r].x
                                 : (sub == 1) ? wv[r].y
                                 : (sub == 2) ? wv[r].z : wv[r].w;
                while (bm) {
                    int l = __ffs(bm) - 1;
                    bm &= bm - 1;
                    float wj = __shfl_sync(0xffffffffu, wsub, l);
                    float2 xv = *(const float2*)(sx + (((l << 2) + sub) << 6) + (lane << 1));
                    accx[r] = fmaf(wj, xv.x, accx[r]);
                    accy[r] = fmaf(wj, xv.y, accy[r]);
                }
            }
        }

        if (hasNext) {
            // W(c+1) predicated prefetch (RPW<=2) — mask latency already paid
            if (RPW <= 2) {
                #pragma unroll
                for (int r = 0; r < RPW; r++) {
                    const size_t be = (size_t)(row0 + r) * N_in + koff + ((c + 1) << 7) + (lane << 2);
                    nib[r] = nibN[r];
                    if (nib[r]) wv[r] = __ldg((const float4*)(W + be));
                }
            } else {
                #pragma unroll
                for (int r = 0; r < RPW; r++) nib[r] = nibN[r];
            }
        }
    }

    float* dst = part + (size_t)blockIdx.y * partElems;
    #pragma unroll
    for (int r = 0; r < RPW; r++) {
        float2 v; v.x = accx[r]; v.y = accy[r];
        *(float2*)(dst + ((size_t)(row0 + r) << 6) + (lane << 1)) = v;
    }
}

// ---------------------------------------------------------------------------
// Combine: out[row][64] = act( sum_s part[s][row][64] + bias[row] )
// one float4 per thread
// ---------------------------------------------------------------------------
__global__ void combine_kernel(const float* __restrict__ part,
                               const float* __restrict__ bias,
                               float* __restrict__ out,
                               int rows, int sk, int relu) {
    int i4 = blockIdx.x * blockDim.x + threadIdx.x;
    int total4 = rows * 16;                 // rows*64/4
    if (i4 >= total4) return;
    int row = i4 >> 4;

    float4 a = ((const float4*)part)[i4];
    for (int s = 1; s < sk; s++) {
        float4 p = ((const float4*)part)[(size_t)s * total4 + i4];
        a.x += p.x; a.y += p.y; a.z += p.z; a.w += p.w;
    }
    float bb = __ldg(bias + row);
    a.x += bb; a.y += bb; a.z += bb; a.w += bb;
    if (relu) {
        a.x = fmaxf(a.x, 0.f); a.y = fmaxf(a.y, 0.f);
        a.z = fmaxf(a.z, 0.f); a.w = fmaxf(a.w, 0.f);
    }
    ((float4*)out)[i4] = a;
}

// ---------------------------------------------------------------------------
// Host launcher
// ---------------------------------------------------------------------------
extern "C" void kernel_launch(void* const* d_in, const int* in_sizes, int n_in,
                              void* d_out, int out_size) {
    static const int S[5] = {512, 2048, 4096, 8192, 16384};

    const float* x = nullptr;
    const float* W[4] = {};
    const float* b[4] = {};
    const void*  m[4] = {};

    for (int i = 0; i < n_in; i++) {
        long sz = (long)in_sizes[i];
        if (sz == 64L * 512L) { if (!x) x = (const float*)d_in[i]; continue; }
        for (int L = 0; L < 4; L++) {
            long wsz = (long)S[L + 1] * (long)S[L];
            if (sz == wsz) {
                if (!W[L]) W[L] = (const float*)d_in[i];
                else if (!m[L]) m[L] = d_in[i];
                break;
            }
            if (sz == (long)S[L + 1]) { b[L] = (const float*)d_in[i]; break; }
        }
    }

    float* bufA = nullptr;
    float* bufB = nullptr;
    float* part = nullptr;
    cudaGetSymbolAddress((void**)&bufA, g_bufA);
    cudaGetSymbolAddress((void**)&bufB, g_bufB);
    cudaGetSymbolAddress((void**)&part, g_part);

    // 1) classify mask dtypes
    detect_dtype_kernel<<<4, 256>>>(m[0], (long)S[1] * S[0],
                                    m[1], (long)S[2] * S[1],
                                    m[2], (long)S[3] * S[2],
                                    m[3], (long)S[4] * S[3]);

    // 2) x [64][512] -> bufA [512][64]
    {
        dim3 tb(32, 8);
        transpose_kernel<<<dim3(16, 2), tb>>>(x, bufA, 64, 512);
    }

    // 3) four layers: split-K sparse partial + combine, ping-pong A->B->A->B->A
    //    layer 0: 512->2048,  RPW1, SK4 (kcols 128)  grid (128,4)
    sparse_partial_kernel<1, 3><<<dim3(128, 4), 512>>>(W[0], m[0], bufA, part,
                                                       S[0], 128, S[1] * 64, 0);
    combine_kernel<<<S[1] * 16 / 256, 256>>>(part, b[0], bufB, S[1], 4, 1);

    //    layer 1: 2048->4096, RPW1, SK2 (kcols 1024) grid (256,2)
    sparse_partial_kernel<1, 3><<<dim3(256, 2), 512>>>(W[1], m[1], bufB, part,
                                                       S[1], 1024, S[2] * 64, 1);
    combine_kernel<<<S[2] * 16 / 256, 256>>>(part, b[1], bufA, S[2], 2, 1);

    //    layer 2: 4096->8192, RPW2, SK2 (kcols 2048) grid (256,2)
    sparse_partial_kernel<2, 3><<<dim3(256, 2), 512>>>(W[2], m[2], bufA, part,
                                                       S[2], 2048, S[3] * 64, 2);
    combine_kernel<<<S[3] * 16 / 256, 256>>>(part, b[2], bufB, S[3], 2, 1);

    //    layer 3: 8192->16384, RPW4, SK2 (kcols 4096) grid (256,2)
    sparse_partial_kernel<4, 2><<<dim3(256, 2), 512>>>(W[3], m[3], bufB, part,
                                                       S[3], 4096, S[4] * 64, 3);
    combine_kernel<<<S[4] * 16 / 256, 256>>>(part, b[3], bufA, S[4], 2, 0);

    // 4) bufA [16384][64] -> d_out [64][16384]
    {
        dim3 tb(32, 8);
        transpose_kernel<<<dim3(2, 512), tb>>>(bufA, (float*)d_out, 16384, 64);
    }
    (void)out_size;
}

// round 9
// speedup vs baseline: 1.2565x; 1.2565x over previous
#include <cuda_runtime.h>
#include <cstdint>
#include <cstddef>

// ---------------------------------------------------------------------------
// SparseDecoder: 4-layer masked MLP, B=64, widths 512->2048->4096->8192->16384
//
// v6 = v4 (proven 537us: simple two-phase chunk body, regs=32) + split-K only.
//      v5's regression traced to its register-heavy pipeline + minBlocks reg
//      cap (spills), NOT split-K. So: identical inner loop to v4, grids of
//      512 CTAs per layer via (rowGroups, SK), partial sums + cheap combine.
// ---------------------------------------------------------------------------

#define MAXN 16384
#define BATCH 64

__device__ float g_bufA[MAXN * BATCH];        // activations, [N][64]
__device__ float g_bufB[MAXN * BATCH];
__device__ float g_part[2 * MAXN * BATCH];    // split-K partials (8 MB)
__device__ int   g_dtype[4];                  // 0=u8, 1=i32, 2=f32, 3=bf16

// ---------------------------------------------------------------------------
// Mask dtype detection (proven).
// ---------------------------------------------------------------------------
__global__ void detect_dtype_kernel(const void* m0, long n0, const void* m1, long n1,
                                    const void* m2, long n2, const void* m3, long n3) {
    const void* ms[4] = {m0, m1, m2, m3};
    long        ns[4] = {n0, n1, n2, n3};
    int L = blockIdx.x;
    const unsigned int* p = (const unsigned int*)ms[L];
    long nw = ns[L] >> 2;
    if (nw > 65536) nw = 65536;

    unsigned int f = 0;
    for (long i = threadIdx.x; i < nw; i += blockDim.x) {
        unsigned int w = __ldg(p + i);
        if (w == 0u) continue;
        if ((w & 0xFFFFu) == 0x3F80u) f |= 1u;                // bf16
        if (w == 0x3F800000u)         f |= 2u;                // f32
        if ((w & 0xFEFEFEFEu) == 0u && w > 1u) f |= 4u;       // u8
        if (w == 1u)                  f |= 8u;                // i32 (or u8 byte0)
    }
    __shared__ unsigned int sf;
    if (threadIdx.x == 0) sf = 0;
    __syncthreads();
    atomicOr(&sf, f);
    __syncthreads();
    if (threadIdx.x == 0) {
        unsigned int ff = sf;
        int dt;
        if      (ff & 1u) dt = 3;
        else if (ff & 2u) dt = 2;
        else if (ff & 4u) dt = 0;
        else if (ff & 8u) dt = 1;
        else              dt = 0;
        g_dtype[L] = dt;
    }
}

// ---------------------------------------------------------------------------
// Tiled transpose: dst[C][R] = src[R][C]
// ---------------------------------------------------------------------------
__global__ void transpose_kernel(const float* __restrict__ src,
                                 float* __restrict__ dst, int R, int C) {
    __shared__ float tile[32][33];
    int c0 = blockIdx.x * 32;
    int r0 = blockIdx.y * 32;
    int tx = threadIdx.x, ty = threadIdx.y;
    #pragma unroll
    for (int i = ty; i < 32; i += 8) {
        int r = r0 + i, c = c0 + tx;
        if (r < R && c < C) tile[i][tx] = src[(size_t)r * C + c];
    }
    __syncthreads();
    #pragma unroll
    for (int i = ty; i < 32; i += 8) {
        int c = c0 + i, r = r0 + tx;
        if (c < C && r < R) dst[(size_t)c * R + r] = tile[tx][i];
    }
}

// ---------------------------------------------------------------------------
// mask element index -> 4-bit nonzero nibble for lane's 4 columns
// ---------------------------------------------------------------------------
__device__ __forceinline__ unsigned int load_nib(const void* mask, size_t eidx, int dt) {
    if (dt == 0) {               // u8
        unsigned int v = __ldg((const unsigned int*)((const unsigned char*)mask + eidx));
        unsigned int c = __vcmpne4(v, 0u);
        return (c & 1u) | ((c >> 7) & 2u) | ((c >> 14) & 4u) | ((c >> 21) & 8u);
    } else if (dt == 3) {        // bf16
        uint2 v = __ldg((const uint2*)((const unsigned short*)mask + eidx));
        return (unsigned)((v.x & 0xFFFFu) != 0u)
             | ((unsigned)((v.x >> 16)     != 0u) << 1)
             | ((unsigned)((v.y & 0xFFFFu) != 0u) << 2)
             | ((unsigned)((v.y >> 16)     != 0u) << 3);
    } else {                     // i32 / f32
        uint4 v = __ldg((const uint4*)((const unsigned int*)mask + eidx));
        return (unsigned)(v.x != 0u)
             | ((unsigned)(v.y != 0u) << 1)
             | ((unsigned)(v.z != 0u) << 2)
             | ((unsigned)(v.w != 0u) << 3);
    }
}

// ---------------------------------------------------------------------------
// Split-K sparse partial (v4 inner loop, unchanged):
//   part[s][rows][64] = (W*mask)[rows, koff:koff+kcols] @ x[koff:koff+kcols]
// grid = (rowGroups, SK). 512 threads = 16 warps; warp owns RPW rows;
// lane owns batch elements 2l, 2l+1.
// ---------------------------------------------------------------------------
template <int RPW>
__global__ __launch_bounds__(512)
void sparse_partial_kernel(const float* __restrict__ W,
                           const void*  __restrict__ mask,
                           const float* __restrict__ xin,   // [N_in][64]
                           float*       __restrict__ part,  // [SK][N_out][64]
                           int N_in, int kcols, int partElems, int layer) {
    __shared__ float sx[128 * 64];   // 32 KB x chunk

    const int tid  = threadIdx.x;
    const int lane = tid & 31;
    const int wid  = tid >> 5;                      // 0..15
    const int row0 = blockIdx.x * (RPW * 16) + wid * RPW;
    const int koff = blockIdx.y * kcols;
    const int dt   = g_dtype[layer];

    float accx[RPW], accy[RPW];
    #pragma unroll
    for (int r = 0; r < RPW; r++) { accx[r] = 0.f; accy[r] = 0.f; }

    for (int c0 = koff; c0 < koff + kcols; c0 += 128) {
        __syncthreads();   // previous chunk fully consumed
        {
            const float4* src  = (const float4*)(xin + (size_t)c0 * BATCH);
            float4*       dst4 = (float4*)sx;
            #pragma unroll
            for (int i = 0; i < 4; i++)            // 2048 float4 / 512 threads
                dst4[tid + i * 512] = __ldg(src + tid + i * 512);
        }
        __syncthreads();

        // ---- phase 1: issue all mask + W loads for this chunk (MLP = 2*RPW)
        unsigned int nib[RPW];
        float4       wv[RPW];
        #pragma unroll
        for (int r = 0; r < RPW; r++) {
            const size_t base = (size_t)(row0 + r) * N_in + c0 + (lane << 2);
            nib[r] = load_nib(mask, base, dt);
            if (nib[r]) wv[r] = __ldg((const float4*)(W + base));
        }

        // ---- phase 2: ballot extraction; W via shfl, x via conflict-free LDS
        #pragma unroll
        for (int r = 0; r < RPW; r++) {
            #pragma unroll
            for (int sub = 0; sub < 4; ++sub) {
                unsigned int bm = __ballot_sync(0xffffffffu, (nib[r] >> sub) & 1u);
                const float wsub = (sub == 0) ? wv[r].x
                                 : (sub == 1) ? wv[r].y
                                 : (sub == 2) ? wv[r].z : wv[r].w;
                while (bm) {
                    int l = __ffs(bm) - 1;
                    bm &= bm - 1;
                    float wj = __shfl_sync(0xffffffffu, wsub, l);
                    float2 xv = *(const float2*)(sx + ((((c0 - koff) & 0) + (l << 2) + sub) << 6) + (lane << 1));
                    accx[r] = fmaf(wj, xv.x, accx[r]);
                    accy[r] = fmaf(wj, xv.y, accy[r]);
                }
            }
        }
    }

    float* dst = part + (size_t)blockIdx.y * partElems;
    #pragma unroll
    for (int r = 0; r < RPW; r++) {
        float2 v; v.x = accx[r]; v.y = accy[r];
        *(float2*)(dst + ((size_t)(row0 + r) << 6) + (lane << 1)) = v;
    }
}

// ---------------------------------------------------------------------------
// Combine: out[row][64] = act( sum_s part[s][row][64] + bias[row] )
// ---------------------------------------------------------------------------
__global__ void combine_kernel(const float* __restrict__ part,
                               const float* __restrict__ bias,
                               float* __restrict__ out,
                               int rows, int sk, int relu) {
    int i4 = blockIdx.x * blockDim.x + threadIdx.x;
    int total4 = rows * 16;                 // rows*64/4
    if (i4 >= total4) return;
    int row = i4 >> 4;

    float4 a = ((const float4*)part)[i4];
    for (int s = 1; s < sk; s++) {
        float4 p = ((const float4*)part)[(size_t)s * total4 + i4];
        a.x += p.x; a.y += p.y; a.z += p.z; a.w += p.w;
    }
    float bb = __ldg(bias + row);
    a.x += bb; a.y += bb; a.z += bb; a.w += bb;
    if (relu) {
        a.x = fmaxf(a.x, 0.f); a.y = fmaxf(a.y, 0.f);
        a.z = fmaxf(a.z, 0.f); a.w = fmaxf(a.w, 0.f);
    }
    ((float4*)out)[i4] = a;
}

// ---------------------------------------------------------------------------
// Host launcher
// ---------------------------------------------------------------------------
extern "C" void kernel_launch(void* const* d_in, const int* in_sizes, int n_in,
                              void* d_out, int out_size) {
    static const int S[5] = {512, 2048, 4096, 8192, 16384};

    const float* x = nullptr;
    const float* W[4] = {};
    const float* b[4] = {};
    const void*  m[4] = {};

    for (int i = 0; i < n_in; i++) {
        long sz = (long)in_sizes[i];
        if (sz == 64L * 512L) { if (!x) x = (const float*)d_in[i]; continue; }
        for (int L = 0; L < 4; L++) {
            long wsz = (long)S[L + 1] * (long)S[L];
            if (sz == wsz) {
                if (!W[L]) W[L] = (const float*)d_in[i];
                else if (!m[L]) m[L] = d_in[i];
                break;
            }
            if (sz == (long)S[L + 1]) { b[L] = (const float*)d_in[i]; break; }
        }
    }

    float* bufA = nullptr;
    float* bufB = nullptr;
    float* part = nullptr;
    cudaGetSymbolAddress((void**)&bufA, g_bufA);
    cudaGetSymbolAddress((void**)&bufB, g_bufB);
    cudaGetSymbolAddress((void**)&part, g_part);

    // 1) classify mask dtypes
    detect_dtype_kernel<<<4, 256>>>(m[0], (long)S[1] * S[0],
                                    m[1], (long)S[2] * S[1],
                                    m[2], (long)S[3] * S[2],
                                    m[3], (long)S[4] * S[3]);

    // 2) x [64][512] -> bufA [512][64]
    {
        dim3 tb(32, 8);
        transpose_kernel<<<dim3(16, 2), tb>>>(x, bufA, 64, 512);
    }

    // 3) layers: split-K partials (512 CTAs each) + combine. A->B->A->B->A
    //    L0: 512->2048,  RPW1, SK4 (kcols 128)   grid (128,4)
    sparse_partial_kernel<1><<<dim3(128, 4), 512>>>(W[0], m[0], bufA, part,
                                                    S[0], 128, S[1] * 64, 0);
    combine_kernel<<<S[1] * 16 / 256, 256>>>(part, b[0], bufB, S[1], 4, 1);

    //    L1: 2048->4096, RPW1, SK2 (kcols 1024)  grid (256,2)
    sparse_partial_kernel<1><<<dim3(256, 2), 512>>>(W[1], m[1], bufB, part,
                                                    S[1], 1024, S[2] * 64, 1);
    combine_kernel<<<S[2] * 16 / 256, 256>>>(part, b[1], bufA, S[2], 2, 1);

    //    L2: 4096->8192, RPW2, SK2 (kcols 2048)  grid (256,2)
    sparse_partial_kernel<2><<<dim3(256, 2), 512>>>(W[2], m[2], bufA, part,
                                                    S[2], 2048, S[3] * 64, 2);
    combine_kernel<<<S[3] * 16 / 256, 256>>>(part, b[2], bufB, S[3], 2, 1);

    //    L3: 8192->16384, RPW4, SK2 (kcols 4096) grid (256,2)
    sparse_partial_kernel<4><<<dim3(256, 2), 512>>>(W[3], m[3], bufB, part,
                                                    S[3], 4096, S[4] * 64, 3);
    combine_kernel<<<S[4] * 16 / 256, 256>>>(part, b[3], bufA, S[4], 2, 0);

    // 4) bufA [16384][64] -> d_out [64][16384]
    {
        dim3 tb(32, 8);
        transpose_kernel<<<dim3(2, 512), tb>>>(bufA, (float*)d_out, 16384, 64);
    }
    (void)out_size;
}